// round 12
// baseline (speedup 1.0000x reference)
#include <cuda_runtime.h>
#include <mma.h>
#include <cstdint>

using namespace nvcuda;

// Problem constants (fixed by setup_inputs)
#define BATCH   16
#define SEQ     4096
#define TOKENS  (BATCH * SEQ)      // 65536
#define C_DIM   256
#define N_QKV   768                // per-branch qkv width
#define N_ALL   2304               // 3 branches merged along N

// Scratch (allocation-free: __device__ globals)
__device__ float g_qkv[(size_t)TOKENS * N_ALL];     // [token][br*768 + {q,k,v}]
__device__ float g_comb[(size_t)TOKENS * C_DIM];    // [token][256] (tf32-rounded)
__device__ float g_x32[(size_t)TOKENS * C_DIM];     // x rounded to tf32
__device__ float g_wq32[(size_t)C_DIM * N_ALL];     // Wqkv repacked+rounded: [k][br*768+n]
__device__ float g_wp32[(size_t)C_DIM * C_DIM];     // Wproj rounded to tf32

__device__ __forceinline__ float to_tf32(float x) {
    unsigned r;
    asm("cvt.rna.tf32.f32 %0, %1;" : "=r"(r) : "f"(x));
    return __uint_as_float(r);
}

// ---------------------------------------------------------------------------
// cp.async helpers
// ---------------------------------------------------------------------------
__device__ __forceinline__ void cp_async16(float* smem_dst, const float* gsrc) {
    uint32_t s = (uint32_t)__cvta_generic_to_shared(smem_dst);
    asm volatile("cp.async.cg.shared.global [%0], [%1], 16;\n" :: "r"(s), "l"(gsrc));
}
__device__ __forceinline__ void cp_commit() {
    asm volatile("cp.async.commit_group;\n");
}
template <int NN>
__device__ __forceinline__ void cp_wait() {
    asm volatile("cp.async.wait_group %0;\n" :: "n"(NN));
}

// ---------------------------------------------------------------------------
// Elementwise tf32 rounding pass (float4 vectorized)
// ---------------------------------------------------------------------------
__global__ __launch_bounds__(256) void round_tf32(const float4* __restrict__ in,
                                                  float4* __restrict__ out,
                                                  size_t n4)
{
    size_t i = (size_t)blockIdx.x * blockDim.x + threadIdx.x;
    size_t stride = (size_t)gridDim.x * blockDim.x;
    for (; i < n4; i += stride) {
        float4 v = in[i];
        v.x = to_tf32(v.x); v.y = to_tf32(v.y);
        v.z = to_tf32(v.z); v.w = to_tf32(v.w);
        out[i] = v;
    }
}

// ---------------------------------------------------------------------------
// Repack Wqkv [3][256][768] -> [256][2304] (branch-major within row), tf32.
// ---------------------------------------------------------------------------
__global__ __launch_bounds__(256) void repack_wqkv(const float4* __restrict__ in,
                                                   float4* __restrict__ out)
{
    int idx = blockIdx.x * 256 + threadIdx.x;     // < 147456
    const int n4 = N_QKV / 4;                     // 192
    int br  = idx / (C_DIM * n4);
    int rem = idx % (C_DIM * n4);
    int k   = rem / n4;
    int c4  = rem % n4;
    float4 v = in[idx];
    v.x = to_tf32(v.x); v.y = to_tf32(v.y);
    v.z = to_tf32(v.z); v.w = to_tf32(v.w);
    out[(size_t)k * (N_ALL / 4) + br * n4 + c4] = v;
}

// ---------------------------------------------------------------------------
// tf32 WMMA GEMM, 3-stage cp.async pipeline, 512 threads:
//   C = A(MxK row-major, tf32-rounded) * B(KxN row-major, tf32-rounded)
// Block tile 128x128, BK=32. 16 warps (4x4), warp tile 32x32 (2x2 frags).
// If bias != nullptr, epilogue adds bias[col] (smem-staged store).
// ---------------------------------------------------------------------------
#define BM 128
#define BN 128
#define BK 32

#define A_STRIDE 36                   // floats per A smem row
#define B_STRIDE 132                  // floats per B smem row
#define A_STAGE  (BM * A_STRIDE)      // 4608 floats
#define B_STAGE  (BK * B_STRIDE)      // 4224 floats
#define STAGE_FLOATS (A_STAGE + B_STAGE)          // 8832 floats = 35328 B
#define NSTAGE 3
#define SMEM_FLOATS (NSTAGE * STAGE_FLOATS)       // 26496 floats = 105984 B

__global__ __launch_bounds__(512, 2) void gemm_tf32_async(
    const float* __restrict__ A, const float* __restrict__ B,
    float* __restrict__ Co, int M, int N, int K,
    const float* __restrict__ bias)
{
    extern __shared__ float smem[];

    const int tileM = blockIdx.y;
    const int tileN = blockIdx.x;
    const int tid   = threadIdx.x;
    const int warp  = tid >> 5;    // 0..15
    const int lane  = tid & 31;
    const int wy    = warp >> 2;   // 0..3  (32 rows each)
    const int wx    = warp & 3;    // 0..3  (32 cols each)

    // Loader coordinates (512 threads; 2 float4 each for A and B per stage)
    const int ar  = tid >> 3;      // A row 0..63  (p adds 64)
    const int ac4 = tid & 7;       // A float4 col
    const int br  = tid >> 5;      // B row 0..15  (p adds 16)
    const int bc4 = tid & 31;      // B float4 col

    const float* Ag = A + (size_t)(tileM * BM + ar) * K + ac4 * 4;
    const float* Bg = B + (size_t)br * N + tileN * BN + bc4 * 4;

    wmma::fragment<wmma::accumulator, 16, 16, 8, float> acc[2][2];
    #pragma unroll
    for (int i = 0; i < 2; i++)
        #pragma unroll
        for (int j = 0; j < 2; j++)
            wmma::fill_fragment(acc[i][j], 0.0f);

    const int nk = K / BK;   // 8 for K=256

    auto fill = [&](int stage, int chunk) {
        float* As = smem + stage * STAGE_FLOATS;
        float* Bs = As + A_STAGE;
        int k0 = chunk * BK;
        #pragma unroll
        for (int p = 0; p < 2; p++)
            cp_async16(As + (ar + p * 64) * A_STRIDE + ac4 * 4,
                       Ag + k0 + (size_t)(p * 64) * K);
        #pragma unroll
        for (int p = 0; p < 2; p++)
            cp_async16(Bs + (br + p * 16) * B_STRIDE + bc4 * 4,
                       Bg + (size_t)(k0 + p * 16) * N);
        cp_commit();
    };

    // Prologue: fill all 3 stages (nk is always >= 3 here)
    fill(0, 0);
    fill(1, 1);
    fill(2, 2);

    for (int kt = 0; kt < nk; kt++) {
        // Ensure chunk kt's group has landed (keep up to 2 newer in flight)
        {
            int rem = nk - 1 - kt;
            if (rem >= 2) cp_wait<2>();
            else if (rem == 1) cp_wait<1>();
            else cp_wait<0>();
        }
        __syncthreads();

        // Compute stage kt
        float* Ac = smem + (kt % NSTAGE) * STAGE_FLOATS;
        float* Bc = Ac + A_STAGE;
        #pragma unroll
        for (int ks = 0; ks < BK; ks += 8) {
            wmma::fragment<wmma::matrix_a, 16, 16, 8, wmma::precision::tf32, wmma::row_major> af[2];
            wmma::fragment<wmma::matrix_b, 16, 16, 8, wmma::precision::tf32, wmma::row_major> bf[2];
            #pragma unroll
            for (int i = 0; i < 2; i++)
                wmma::load_matrix_sync(af[i], Ac + (wy * 32 + i * 16) * A_STRIDE + ks, A_STRIDE);
            #pragma unroll
            for (int j = 0; j < 2; j++)
                wmma::load_matrix_sync(bf[j], Bc + ks * B_STRIDE + wx * 32 + j * 16, B_STRIDE);
            #pragma unroll
            for (int i = 0; i < 2; i++)
                #pragma unroll
                for (int j = 0; j < 2; j++)
                    wmma::mma_sync(acc[i][j], af[i], bf[j], acc[i][j]);
        }
        __syncthreads();   // all warps done with stage kt%3 before refill

        if (kt + 3 < nk) fill(kt % NSTAGE, kt + 3);
    }

    if (bias == nullptr) {
        #pragma unroll
        for (int i = 0; i < 2; i++)
            #pragma unroll
            for (int j = 0; j < 2; j++) {
                int r0 = tileM * BM + wy * 32 + i * 16;
                int c0 = tileN * BN + wx * 32 + j * 16;
                wmma::store_matrix_sync(Co + (size_t)r0 * N + c0, acc[i][j], N,
                                        wmma::mem_row_major);
            }
    } else {
        // Smem staging (pipeline smem reusable after final loop sync)
        float* epi = smem + warp * 256;
        const int er = lane >> 1;            // row 0..15
        const int ec = (lane & 1) * 8;       // col 0 or 8
        #pragma unroll
        for (int i = 0; i < 2; i++)
            #pragma unroll
            for (int j = 0; j < 2; j++) {
                wmma::store_matrix_sync(epi, acc[i][j], 16, wmma::mem_row_major);
                __syncwarp();
                int gr = tileM * BM + wy * 32 + i * 16 + er;
                int gc = tileN * BN + wx * 32 + j * 16 + ec;
                float4 v0 = *(float4*)(epi + er * 16 + ec);
                float4 v1 = *(float4*)(epi + er * 16 + ec + 4);
                float4 b0 = __ldg((const float4*)(bias + gc));
                float4 b1 = __ldg((const float4*)(bias + gc + 4));
                v0.x += b0.x; v0.y += b0.y; v0.z += b0.z; v0.w += b0.w;
                v1.x += b1.x; v1.y += b1.y; v1.z += b1.z; v1.w += b1.w;
                *(float4*)(Co + (size_t)gr * N + gc)     = v0;
                *(float4*)(Co + (size_t)gr * N + gc + 4) = v1;
                __syncwarp();
            }
    }
}

// ---------------------------------------------------------------------------
// Dilated local attention (K=3 taps, dilations 1,2,3), mean over 3 branches.
// One warp per token; lane owns 8 channels. Reads g_qkv (merged layout:
// token-major, 2304 floats/token), writes g_comb (tf32-rounded).
// Reference zero-pads: out-of-range taps contribute logit 0 and value 0.
// ---------------------------------------------------------------------------
__global__ __launch_bounds__(256) void attn_kernel()
{
    const int lane = threadIdx.x & 31;
    const int t    = blockIdx.x * 8 + (threadIdx.x >> 5);   // token
    const int n    = t & (SEQ - 1);                         // pos within batch
    const float scale = 0.0625f;                            // 256^-0.5

    float out[8];
    #pragma unroll
    for (int c = 0; c < 8; c++) out[c] = 0.0f;

    const float* tok = g_qkv + (size_t)t * N_ALL;

    #pragma unroll
    for (int br = 0; br < 3; br++) {
        const int d = br + 1;
        const float* base = tok + br * N_QKV;

        float q[8];
        {
            float4 a = *(const float4*)(base + lane * 8);
            float4 b = *(const float4*)(base + lane * 8 + 4);
            q[0]=a.x; q[1]=a.y; q[2]=a.z; q[3]=a.w;
            q[4]=b.x; q[5]=b.y; q[6]=b.z; q[7]=b.w;
        }

        float lg[3];
        float vv[3][8];
        #pragma unroll
        for (int j = 0; j < 3; j++) {
            int off = (j - 1) * d;
            bool ok = ((unsigned)(n + off) < (unsigned)SEQ);
            float dot = 0.0f;
            if (ok) {
                const float* kr = base + (ptrdiff_t)off * N_ALL + C_DIM;
                float4 k0 = *(const float4*)(kr + lane * 8);
                float4 k1 = *(const float4*)(kr + lane * 8 + 4);
                dot = q[0]*k0.x + q[1]*k0.y + q[2]*k0.z + q[3]*k0.w
                    + q[4]*k1.x + q[5]*k1.y + q[6]*k1.z + q[7]*k1.w;
                const float* vr = base + (ptrdiff_t)off * N_ALL + 2 * C_DIM;
                float4 v0 = *(const float4*)(vr + lane * 8);
                float4 v1 = *(const float4*)(vr + lane * 8 + 4);
                vv[j][0]=v0.x; vv[j][1]=v0.y; vv[j][2]=v0.z; vv[j][3]=v0.w;
                vv[j][4]=v1.x; vv[j][5]=v1.y; vv[j][6]=v1.z; vv[j][7]=v1.w;
            } else {
                #pragma unroll
                for (int c = 0; c < 8; c++) vv[j][c] = 0.0f;
            }
            lg[j] = dot;   // 0 when out-of-range (zero-padded k row)
        }

        #pragma unroll
        for (int s = 16; s > 0; s >>= 1) {
            lg[0] += __shfl_xor_sync(0xffffffffu, lg[0], s);
            lg[1] += __shfl_xor_sync(0xffffffffu, lg[1], s);
            lg[2] += __shfl_xor_sync(0xffffffffu, lg[2], s);
        }
        lg[0] *= scale; lg[1] *= scale; lg[2] *= scale;

        float m  = fmaxf(lg[0], fmaxf(lg[1], lg[2]));
        float e0 = expf(lg[0] - m);
        float e1 = expf(lg[1] - m);
        float e2 = expf(lg[2] - m);
        float inv = 1.0f / (e0 + e1 + e2);
        float a0 = e0 * inv, a1 = e1 * inv, a2 = e2 * inv;

        #pragma unroll
        for (int c = 0; c < 8; c++)
            out[c] += a0 * vv[0][c] + a1 * vv[1][c] + a2 * vv[2][c];
    }

    const float third = 1.0f / 3.0f;
    float4 o0, o1;
    o0.x = to_tf32(out[0]*third); o0.y = to_tf32(out[1]*third);
    o0.z = to_tf32(out[2]*third); o0.w = to_tf32(out[3]*third);
    o1.x = to_tf32(out[4]*third); o1.y = to_tf32(out[5]*third);
    o1.z = to_tf32(out[6]*third); o1.w = to_tf32(out[7]*third);
    float* dst = g_comb + (size_t)t * C_DIM + lane * 8;
    *(float4*)(dst)     = o0;
    *(float4*)(dst + 4) = o1;
}

// ---------------------------------------------------------------------------
// kernel_launch
// Inputs: d_in[0]=x (16,4096,256) f32, d_in[1]=Wqkv (3,256,768) f32,
//         d_in[2]=Wproj (256,256) f32, d_in[3]=bproj (256,) f32
// Output: (16,4096,256) f32
// ---------------------------------------------------------------------------
extern "C" void kernel_launch(void* const* d_in, const int* in_sizes, int n_in,
                              void* d_out, int out_size)
{
    const float* x     = (const float*)d_in[0];
    const float* Wqkv  = (const float*)d_in[1];
    const float* Wproj = (const float*)d_in[2];
    const float* bproj = (const float*)d_in[3];
    float*       out   = (float*)d_out;

    float *qkv, *comb, *x32, *wq32, *wp32;
    cudaGetSymbolAddress((void**)&qkv,  g_qkv);
    cudaGetSymbolAddress((void**)&comb, g_comb);
    cudaGetSymbolAddress((void**)&x32,  g_x32);
    cudaGetSymbolAddress((void**)&wq32, g_wq32);
    cudaGetSymbolAddress((void**)&wp32, g_wp32);

    static bool attr_done = false;
    if (!attr_done) {
        cudaFuncSetAttribute(gemm_tf32_async,
                             cudaFuncAttributeMaxDynamicSharedMemorySize,
                             SMEM_FLOATS * sizeof(float));
        attr_done = true;
    }

    // 0) Round inputs to tf32 once; repack Wqkv into merged-N layout
    round_tf32<<<2048, 256>>>((const float4*)x, (float4*)x32,
                              (size_t)TOKENS * C_DIM / 4);
    repack_wqkv<<<576, 256>>>((const float4*)Wqkv, (float4*)wq32);
    round_tf32<<<16, 256>>>((const float4*)Wproj, (float4*)wp32,
                            (size_t)C_DIM * C_DIM / 4);

    // 1) Merged QKV GEMM: (65536x256) @ (256x2304)
    {
        dim3 grid(N_ALL / BN, TOKENS / BM, 1);
        gemm_tf32_async<<<grid, 512, SMEM_FLOATS * sizeof(float)>>>(
            x32, wq32, qkv, TOKENS, N_ALL, C_DIM, nullptr);
    }

    // 2) Fused dilated local attention + mean over branches
    attn_kernel<<<TOKENS / 8, 256>>>();

    // 3) Proj GEMM with fused bias: (65536x256) @ (256x256) + b -> out
    {
        dim3 grid(C_DIM / BN, TOKENS / BM, 1);
        gemm_tf32_async<<<grid, 512, SMEM_FLOATS * sizeof(float)>>>(
            comb, wp32, out, TOKENS, C_DIM, C_DIM, bproj);
    }
}